// round 2
// baseline (speedup 1.0000x reference)
#include <cuda_runtime.h>
#include <math.h>

// Problem constants (fixed by reference setup_inputs)
#define BB 4
#define HH 8
#define SS 2048
#define DD 8
#define CAP 32   // max candidates on the warp-parallel fast path (lane per candidate)

// Monotone global: max ||x_row||^2 over all 65536 (b,h,s) rows, as float bits.
// Zero-initialized at module load; inputs are fixed, so the value is
// deterministic across the correctness run, capture, and every replay.
__device__ unsigned g_xn2;

// ---------------------------------------------------------------------------
// Kernel 1: max row-norm^2 of x. One thread per (b,h,s) row of 8 floats.
// ---------------------------------------------------------------------------
__global__ void k_xmax(const float* __restrict__ x) {
    int row = blockIdx.x * blockDim.x + threadIdx.x;   // < BB*HH*SS = 65536
    const float4* xr = (const float4*)(x + (size_t)row * DD);
    float4 a = xr[0], b = xr[1];
    float n = a.x*a.x + a.y*a.y + a.z*a.z + a.w*a.w
            + b.x*b.x + b.y*b.y + b.z*b.z + b.w*b.w;
#pragma unroll
    for (int o = 16; o; o >>= 1)
        n = fmaxf(n, __shfl_xor_sync(0xffffffffu, n, o));
    if ((threadIdx.x & 31) == 0)
        atomicMax(&g_xn2, __float_as_uint(n));         // n >= 0: uint order == float order
}

// ---------------------------------------------------------------------------
// Kernel 2: fused candidate-scan + projection + softmax + output.
// One block (256 threads) per (b,q) row. Mask row (2048 floats) read once.
// Warp w handles head w: q,k computed on the fly from x and the 8x8 weights.
// ---------------------------------------------------------------------------
__global__ void __launch_bounds__(256) k_fused(
        const float* __restrict__ x, const float* __restrict__ mask,
        const float* __restrict__ Wq, const float* __restrict__ bq,
        const float* __restrict__ Wk, const float* __restrict__ bk,
        float* __restrict__ out) {
    int row = blockIdx.x;                  // b*SS + q
    int b   = row >> 11;
    int q   = row & (SS - 1);
    int t   = threadIdx.x;

    __shared__ float sWq[64], sWk[64], sbq[8], sbk[8];
    __shared__ float warpmin[8];
    __shared__ float s_thresh;
    __shared__ int   s_cnt;
    __shared__ int   s_idx[CAP];
    __shared__ float s_mv[CAP];

    if (t < 64)                sWq[t]       = Wq[t];
    else if (t < 128)          sWk[t - 64]  = Wk[t - 64];
    else if (t < 136)          sbq[t - 128] = bq[t - 128];
    else if (t < 144)          sbk[t - 136] = bk[t - 136];

    // ---- Phase 1: mask row scan (the only big memory stream) ----
    const float4* mr = (const float4*)(mask + (size_t)row * SS);
    float4 m0 = mr[t * 2], m1 = mr[t * 2 + 1];
    float v[8] = {m0.x, m0.y, m0.z, m0.w, m1.x, m1.y, m1.z, m1.w};

    float mn = v[0];
#pragma unroll
    for (int j = 1; j < 8; j++) mn = fminf(mn, v[j]);
#pragma unroll
    for (int o = 16; o; o >>= 1) mn = fminf(mn, __shfl_xor_sync(0xffffffffu, mn, o));
    if ((t & 31) == 0) warpmin[t >> 5] = mn;
    __syncthreads();

    if (t == 0) {
        float m = warpmin[0];
#pragma unroll
        for (int i = 1; i < 8; i++) m = fminf(m, warpmin[i]);
        // Rigorous score bound: |q.k|/sqrt(8) <= (|Wq|_F xm + |bq|)(|Wk|_F xm + |bk|)/sqrt(8)
        float fq = 0.f, fk = 0.f, nbq = 0.f, nbk = 0.f;
#pragma unroll
        for (int i = 0; i < 64; i++) { fq += sWq[i]*sWq[i]; fk += sWk[i]*sWk[i]; }
#pragma unroll
        for (int i = 0; i < 8; i++)  { nbq += sbq[i]*sbq[i]; nbk += sbk[i]*sbk[i]; }
        float xm = sqrtf(__uint_as_float(g_xn2));
        float qb = (sqrtf(fq)*xm + sqrtf(nbq)) * (sqrtf(fk)*xm + sqrtf(nbk)) * 0.35355339059f;
        // keys above this threshold carry >= 30 nats less weight than the best key
        s_thresh = m + (2.0f * qb + 30.0f) * 1e-4f;
        s_cnt = 0;
    }
    __syncthreads();

    float th = s_thresh;
#pragma unroll
    for (int j = 0; j < 8; j++) {
        if (v[j] <= th) {
            int p = atomicAdd(&s_cnt, 1);
            if (p < CAP) { s_idx[p] = t * 8 + j; s_mv[p] = v[j]; }
        }
    }
    __syncthreads();

    // ---- Phase 2: per-head attention. Warp w = head w. ----
    int w    = t >> 5;
    int lane = t & 31;
    int bh   = b * HH + w;
    const float* xb = x + (size_t)bh * SS * DD;

    // full q vector on every lane (cheap: 8-float broadcast load + 64 FMA)
    const float4* xq = (const float4*)(xb + (size_t)q * DD);
    float4 a0 = xq[0], a1 = xq[1];
    float xv[8] = {a0.x, a0.y, a0.z, a0.w, a1.x, a1.y, a1.z, a1.w};
    float qv[8];
#pragma unroll
    for (int i = 0; i < 8; i++) {
        float s = sbq[i];
#pragma unroll
        for (int j = 0; j < 8; j++) s += xv[j] * sWq[i*8 + j];
        qv[i] = s;
    }

    int   cnt = s_cnt;
    float acc[8];
    float inv;

    if (cnt <= CAP) {
        // fast path: lane i = candidate i, all gathers in flight at once
        float score = -INFINITY;
        float xk[8] = {0,0,0,0,0,0,0,0};
        if (lane < cnt) {
            int kk = s_idx[lane];
            const float4* xr = (const float4*)(xb + (size_t)kk * DD);
            float4 c0 = xr[0], c1 = xr[1];
            xk[0]=c0.x; xk[1]=c0.y; xk[2]=c0.z; xk[3]=c0.w;
            xk[4]=c1.x; xk[5]=c1.y; xk[6]=c1.z; xk[7]=c1.w;
            float sdot = 0.f;
#pragma unroll
            for (int i = 0; i < 8; i++) {
                float kv = sbk[i];
#pragma unroll
                for (int j = 0; j < 8; j++) kv += xk[j] * sWk[i*8 + j];
                sdot += qv[i] * kv;
            }
            score = sdot * 0.35355339059f - 10000.0f * s_mv[lane];
        }
        float m = score;
#pragma unroll
        for (int o = 16; o; o >>= 1) m = fmaxf(m, __shfl_xor_sync(0xffffffffu, m, o));
        float p = (lane < cnt) ? expf(score - m) : 0.f;
        float l = p;
#pragma unroll
        for (int o = 16; o; o >>= 1) l += __shfl_xor_sync(0xffffffffu, l, o);
#pragma unroll
        for (int i = 0; i < 8; i++) {
            float s = p * xk[i];
#pragma unroll
            for (int o = 16; o; o >>= 1) s += __shfl_xor_sync(0xffffffffu, s, o);
            acc[i] = s;
        }
        inv = 1.0f / l;
    } else {
        // exact full-row fallback (vanishingly rare): online softmax, lanes stride keys
        const float* mrow = mask + (size_t)row * SS;
        float m = -INFINITY, l = 0.f;
#pragma unroll
        for (int i = 0; i < 8; i++) acc[i] = 0.f;
        for (int kk = lane; kk < SS; kk += 32) {
            const float4* xr = (const float4*)(xb + (size_t)kk * DD);
            float4 c0 = xr[0], c1 = xr[1];
            float xk[8] = {c0.x,c0.y,c0.z,c0.w,c1.x,c1.y,c1.z,c1.w};
            float sdot = 0.f;
#pragma unroll
            for (int i = 0; i < 8; i++) {
                float kv = sbk[i];
#pragma unroll
                for (int j = 0; j < 8; j++) kv += xk[j] * sWk[i*8 + j];
                sdot += qv[i] * kv;
            }
            float sc = sdot * 0.35355339059f - 10000.0f * mrow[kk];
            float nm = fmaxf(m, sc);
            float corr = expf(m - nm);
            float p = expf(sc - nm);
            l = l * corr + p;
#pragma unroll
            for (int i = 0; i < 8; i++) acc[i] = acc[i]*corr + p*xk[i];
            m = nm;
        }
        // warp merge of (m, l, acc)
#pragma unroll
        for (int o = 16; o; o >>= 1) {
            float om = __shfl_xor_sync(0xffffffffu, m, o);
            float ol = __shfl_xor_sync(0xffffffffu, l, o);
            float oa[8];
#pragma unroll
            for (int i = 0; i < 8; i++) oa[i] = __shfl_xor_sync(0xffffffffu, acc[i], o);
            float nm = fmaxf(m, om);
            float c1 = expf(m - nm), c2 = expf(om - nm);
            l = l * c1 + ol * c2;
#pragma unroll
            for (int i = 0; i < 8; i++) acc[i] = acc[i]*c1 + oa[i]*c2;
            m = nm;
        }
        inv = 1.0f / l;
    }

    if (lane == 0) {
        float4* o = (float4*)(out + ((size_t)bh * SS + q) * DD);
        o[0] = make_float4(acc[0]*inv, acc[1]*inv, acc[2]*inv, acc[3]*inv);
        o[1] = make_float4(acc[4]*inv, acc[5]*inv, acc[6]*inv, acc[7]*inv);
    }
}

extern "C" void kernel_launch(void* const* d_in, const int* in_sizes, int n_in,
                              void* d_out, int out_size) {
    const float* x    = (const float*)d_in[0];  // [4,8,2048,8]
    const float* mask = (const float*)d_in[1];  // [4,1,2048,2048]
    const float* Wq   = (const float*)d_in[2];  // [8,8]
    const float* bq   = (const float*)d_in[3];  // [8]
    const float* Wk   = (const float*)d_in[4];  // [8,8]
    const float* bk   = (const float*)d_in[5];  // [8]
    float* out = (float*)d_out;                 // [4,8,2048,8]

    k_xmax<<<(BB*HH*SS)/256, 256>>>(x);
    k_fused<<<BB*SS, 256>>>(x, mask, Wq, bq, Wk, bk, out);
}

// round 3
// speedup vs baseline: 3.1201x; 3.1201x over previous
#include <cuda_runtime.h>
#include <math.h>

// Problem constants (fixed by reference setup_inputs)
#define BB 4
#define HH 8
#define SS 2048
#define DD 8
#define CAP 32

// Scratch. g_xn2 is a monotone max over fixed inputs: zero-initialized at
// module load, identical value after every call -> deterministic.
__device__ unsigned g_xn2;
__device__ float    g_margin;            // threshold window width
__device__ int      g_cnt[BB*SS];        // candidates per (b,q) row
__device__ int      g_cand[BB*SS*CAP];   // candidate key indices (cnt>=2 rows only)
__device__ float    g_mval[BB*SS*CAP];   // their mask values

// ---------------------------------------------------------------------------
// Kernel 1: max row-norm^2 of x over all 65536 (b,h,s) rows.
// ---------------------------------------------------------------------------
__global__ void k_xmax(const float* __restrict__ x) {
    int row = blockIdx.x * blockDim.x + threadIdx.x;
    const float4* xr = (const float4*)(x + (size_t)row * DD);
    float4 a = xr[0], b = xr[1];
    float n = a.x*a.x + a.y*a.y + a.z*a.z + a.w*a.w
            + b.x*b.x + b.y*b.y + b.z*b.z + b.w*b.w;
#pragma unroll
    for (int o = 16; o; o >>= 1)
        n = fmaxf(n, __shfl_xor_sync(0xffffffffu, n, o));
    if ((threadIdx.x & 31) == 0)
        atomicMax(&g_xn2, __float_as_uint(n));   // n >= 0: uint order == float order
}

// ---------------------------------------------------------------------------
// Kernel 2 (1 warp): rigorous candidate-window margin.
// |score| <= (|Wq|_F xm + |bq|)(|Wk|_F xm + |bk|)/sqrt(8) = qb.
// Keys with mask > mask_min + (2 qb + 30)/1e4 carry >= 30 nats less weight
// than the best key -> < e^-30 relative contribution each.
// ---------------------------------------------------------------------------
__global__ void k_prep(const float* __restrict__ Wq, const float* __restrict__ bq,
                       const float* __restrict__ Wk, const float* __restrict__ bk) {
    if (threadIdx.x == 0) {
        float fq = 0.f, fk = 0.f, nbq = 0.f, nbk = 0.f;
        for (int i = 0; i < 64; i++) { fq += Wq[i]*Wq[i]; fk += Wk[i]*Wk[i]; }
        for (int i = 0; i < 8;  i++) { nbq += bq[i]*bq[i]; nbk += bk[i]*bk[i]; }
        float xm = sqrtf(__uint_as_float(g_xn2));
        float qb = (sqrtf(fq)*xm + sqrtf(nbq)) * (sqrtf(fk)*xm + sqrtf(nbk)) * 0.35355339059f;
        g_margin = (2.0f * qb + 30.0f) * 1e-4f;
    }
}

// ---------------------------------------------------------------------------
// Kernel 3: lean mask-row scan. Block per (b,q) row, 256 threads.
// Streams the 64 MB mask exactly once. cnt==1 (~99% of rows): softmax weight
// is exactly 1 -> output rows for all 8 heads are a copy of x at the
// candidate key; done right here. cnt>=2: spill candidates for k_rare.
// ---------------------------------------------------------------------------
__global__ void __launch_bounds__(256) k_scan(
        const float* __restrict__ x, const float* __restrict__ mask,
        float* __restrict__ out) {
    int row = blockIdx.x;               // b*SS + q
    int b   = row >> 11;
    int q   = row & (SS - 1);
    int t   = threadIdx.x;

    __shared__ float warpmin[8];
    __shared__ float s_thresh;
    __shared__ int   s_cnt;
    __shared__ int   s_idx[CAP];
    __shared__ float s_mv[CAP];

    const float4* mr = (const float4*)(mask + (size_t)row * SS);
    float4 m0 = mr[t * 2], m1 = mr[t * 2 + 1];
    float v[8] = {m0.x, m0.y, m0.z, m0.w, m1.x, m1.y, m1.z, m1.w};

    float mn = v[0];
#pragma unroll
    for (int j = 1; j < 8; j++) mn = fminf(mn, v[j]);
#pragma unroll
    for (int o = 16; o; o >>= 1) mn = fminf(mn, __shfl_xor_sync(0xffffffffu, mn, o));
    if ((t & 31) == 0) warpmin[t >> 5] = mn;
    __syncthreads();
    if (t == 0) {
        float m = fminf(fminf(fminf(warpmin[0], warpmin[1]), fminf(warpmin[2], warpmin[3])),
                        fminf(fminf(warpmin[4], warpmin[5]), fminf(warpmin[6], warpmin[7])));
        s_thresh = m + g_margin;
        s_cnt = 0;
    }
    __syncthreads();

    float th = s_thresh;
#pragma unroll
    for (int j = 0; j < 8; j++) {
        if (v[j] <= th) {
            int p = atomicAdd(&s_cnt, 1);
            if (p < CAP) { s_idx[p] = t * 8 + j; s_mv[p] = v[j]; }
        }
    }
    __syncthreads();

    int cnt = s_cnt;
    if (t == 0) g_cnt[row] = cnt;
    if (cnt == 1) {
        // exact: single-key softmax == 1 -> copy x row for each head
        if (t < 16) {
            int h = t >> 1, p = t & 1;
            int kk = s_idx[0];
            size_t base = ((size_t)(b * HH + h) * SS);
            const float4* src = (const float4*)(x   + (base + kk) * DD);
            float4*       dst = (float4*)      (out + (base + q ) * DD);
            dst[p] = src[p];
        }
    } else {
        if (t < cnt && t < CAP) {
            g_cand[(size_t)row * CAP + t] = s_idx[t];
            g_mval[(size_t)row * CAP + t] = s_mv[t];
        }
    }
}

// ---------------------------------------------------------------------------
// Kernel 4: rare rows (cnt >= 2). Thread per (b,h,q); ~99% exit immediately
// after one coalesced cnt load. Active threads compute q/k projections on the
// fly and an exact online softmax over the candidate list (full-row fallback
// if the list overflowed -- still exact).
// ---------------------------------------------------------------------------
__global__ void k_rare(const float* __restrict__ x, const float* __restrict__ mask,
                       const float* __restrict__ Wq, const float* __restrict__ bq,
                       const float* __restrict__ Wk, const float* __restrict__ bk,
                       float* __restrict__ out) {
    int idx = blockIdx.x * blockDim.x + threadIdx.x;  // < BB*HH*SS
    int q   = idx & (SS - 1);
    int bh  = idx >> 11;
    int b   = bh >> 3;
    int rowbq = b * SS + q;

    int cnt = g_cnt[rowbq];
    if (cnt < 2) return;

    const float* xb = x + (size_t)bh * SS * DD;
    const float4* xq = (const float4*)(xb + (size_t)q * DD);
    float4 a0 = xq[0], a1 = xq[1];
    float xv[8] = {a0.x, a0.y, a0.z, a0.w, a1.x, a1.y, a1.z, a1.w};

    float qv[8];
#pragma unroll
    for (int i = 0; i < 8; i++) {
        float s = __ldg(bq + i);
#pragma unroll
        for (int j = 0; j < 8; j++) s += xv[j] * __ldg(Wq + i*8 + j);
        qv[i] = s;
    }
    float kb[8], kw[64];
#pragma unroll
    for (int i = 0; i < 8; i++)  kb[i] = __ldg(bk + i);
#pragma unroll
    for (int i = 0; i < 64; i++) kw[i] = __ldg(Wk + i);

    bool full = (cnt > CAP);
    int n = full ? SS : cnt;
    const int*   cl = g_cand + (size_t)rowbq * CAP;
    const float* mv = g_mval + (size_t)rowbq * CAP;
    const float* mrow = mask + (size_t)rowbq * SS;

    float m = -INFINITY, l = 0.f;
    float acc[8] = {0,0,0,0,0,0,0,0};

    for (int i = 0; i < n; i++) {
        int kk   = full ? i : cl[i];
        float mm = full ? mrow[kk] : mv[i];
        const float4* xr = (const float4*)(xb + (size_t)kk * DD);
        float4 c0 = xr[0], c1 = xr[1];
        float xk[8] = {c0.x,c0.y,c0.z,c0.w,c1.x,c1.y,c1.z,c1.w};
        float sdot = 0.f;
#pragma unroll
        for (int i2 = 0; i2 < 8; i2++) {
            float kv = kb[i2];
#pragma unroll
            for (int j = 0; j < 8; j++) kv += xk[j] * kw[i2*8 + j];
            sdot += qv[i2] * kv;
        }
        float sc = sdot * 0.35355339059f - 10000.0f * mm;
        float nm = fmaxf(m, sc);
        float corr = expf(m - nm);
        float p = expf(sc - nm);
        l = l * corr + p;
#pragma unroll
        for (int i2 = 0; i2 < 8; i2++) acc[i2] = acc[i2]*corr + p*xk[i2];
        m = nm;
    }

    float inv = 1.0f / l;
    float4* o = (float4*)(out + (size_t)idx * DD);
    o[0] = make_float4(acc[0]*inv, acc[1]*inv, acc[2]*inv, acc[3]*inv);
    o[1] = make_float4(acc[4]*inv, acc[5]*inv, acc[6]*inv, acc[7]*inv);
}

extern "C" void kernel_launch(void* const* d_in, const int* in_sizes, int n_in,
                              void* d_out, int out_size) {
    const float* x    = (const float*)d_in[0];  // [4,8,2048,8]
    const float* mask = (const float*)d_in[1];  // [4,1,2048,2048]
    const float* Wq   = (const float*)d_in[2];  // [8,8]
    const float* bq   = (const float*)d_in[3];  // [8]
    const float* Wk   = (const float*)d_in[4];  // [8,8]
    const float* bk   = (const float*)d_in[5];  // [8]
    float* out = (float*)d_out;                 // [4,8,2048,8]

    k_xmax<<<(BB*HH*SS)/256, 256>>>(x);
    k_prep<<<1, 32>>>(Wq, bq, Wk, bk);
    k_scan<<<BB*SS, 256>>>(x, mask, out);
    k_rare<<<(BB*HH*SS)/256, 256>>>(x, mask, Wq, bq, Wk, bk, out);
}